// round 1
// baseline (speedup 1.0000x reference)
#include <cuda_runtime.h>
#include <math.h>

#define NN 10000
#define DD 512
#define HH 256
#define OO 128
#define CAP 128          // max neighbors per row (avg ~15, 6-sigma ~40)
#define LCAP 16          // per-thread local buffer in scan

// ---------------- scratch (static device memory; no allocations) -------------
__device__ int   g_cols[(size_t)NN * CAP];   // neighbor column indices per row
__device__ int   g_cnt [NN];                 // nnz per row (degree = cnt+1)
__device__ float g_dinv[NN];                 // rsqrt(degree)
__device__ float g_xw  [(size_t)NN * HH];    // x @ W1
__device__ float g_h   [(size_t)NN * HH];    // relu(an @ xw)
__device__ float g_g   [(size_t)NN * HH];    // an @ h

// ---------------- Kernel A: adjacency scan -> CSR + dinv ---------------------
// One block (256 threads) per row. Deterministic ordering via prefix scan.
__global__ void k_scan(const float* __restrict__ adj)
{
    const int row = blockIdx.x;
    const int tid = threadIdx.x;
    const float4* __restrict__ arow =
        reinterpret_cast<const float4*>(adj + (size_t)row * NN);

    int local[LCAP];
    int lc = 0;
    #pragma unroll 4
    for (int q = tid; q < NN / 4; q += 256) {
        float4 v = arow[q];
        int b = q * 4;
        if (v.x != 0.0f) { if (lc < LCAP) local[lc] = b + 0; lc++; }
        if (v.y != 0.0f) { if (lc < LCAP) local[lc] = b + 1; lc++; }
        if (v.z != 0.0f) { if (lc < LCAP) local[lc] = b + 2; lc++; }
        if (v.w != 0.0f) { if (lc < LCAP) local[lc] = b + 3; lc++; }
    }
    if (lc > LCAP) lc = LCAP;

    __shared__ int s_c[256];
    __shared__ int s_off[256];
    __shared__ int s_total;
    s_c[tid] = lc;
    __syncthreads();
    if (tid == 0) {                 // serial exclusive scan: 256 adds, negligible
        int acc = 0;
        #pragma unroll 8
        for (int i = 0; i < 256; i++) { s_off[i] = acc; acc += s_c[i]; }
        s_total = acc;
    }
    __syncthreads();

    int* __restrict__ mycols = g_cols + (size_t)row * CAP;
    int pos = s_off[tid];
    for (int i = 0; i < lc; i++) {
        int p = pos + i;
        if (p < CAP) mycols[p] = local[i];
    }
    if (tid == 0) {
        int total = s_total;
        if (total > CAP) total = CAP;
        g_cnt[row]  = total;
        g_dinv[row] = rsqrtf((float)total + 1.0f);   // degree includes self loop
    }
}

// ---------------- Kernel B: fp32 SGEMM  C[M,N] = A[M,K] @ B[K,N] -------------
// BM=BN=128, BK=8, 256 threads, 8x8 per-thread tile. N,K multiples of 8/128 as used.
__global__ __launch_bounds__(256)
void k_sgemm(const float* __restrict__ A, const float* __restrict__ B,
             float* __restrict__ C, int M, int N, int K)
{
    const int BM = 128, BN = 128, BK = 8, TM = 8, TN = 8;
    __shared__ float As[BK][BM];
    __shared__ float Bs[BK][BN];

    const int tid = threadIdx.x;
    const int tx = tid % 16;           // 16 x 16 thread grid
    const int ty = tid / 16;
    const int row0 = blockIdx.y * BM;
    const int col0 = blockIdx.x * BN;

    // load mapping: 1024 floats per tile, 4 per thread (float4)
    const int aIdx = tid * 4;
    const int ar = aIdx / BK;          // 0..127
    const int ac = aIdx % BK;          // 0 or 4
    const int bIdx = tid * 4;
    const int br = bIdx / BN;          // 0..7
    const int bc = bIdx % BN;

    float acc[TM][TN];
    #pragma unroll
    for (int i = 0; i < TM; i++)
        #pragma unroll
        for (int j = 0; j < TN; j++) acc[i][j] = 0.0f;

    for (int k0 = 0; k0 < K; k0 += BK) {
        float4 av = make_float4(0.f, 0.f, 0.f, 0.f);
        if (row0 + ar < M)
            av = *reinterpret_cast<const float4*>(A + (size_t)(row0 + ar) * K + k0 + ac);
        As[ac + 0][ar] = av.x;
        As[ac + 1][ar] = av.y;
        As[ac + 2][ar] = av.z;
        As[ac + 3][ar] = av.w;

        float4 bv = *reinterpret_cast<const float4*>(B + (size_t)(k0 + br) * N + col0 + bc);
        *reinterpret_cast<float4*>(&Bs[br][bc]) = bv;
        __syncthreads();

        #pragma unroll
        for (int k = 0; k < BK; k++) {
            float a[TM], b[TN];
            #pragma unroll
            for (int i = 0; i < TM; i++) a[i] = As[k][ty * TM + i];
            #pragma unroll
            for (int j = 0; j < TN; j++) b[j] = Bs[k][tx * TN + j];
            #pragma unroll
            for (int i = 0; i < TM; i++)
                #pragma unroll
                for (int j = 0; j < TN; j++)
                    acc[i][j] += a[i] * b[j];
        }
        __syncthreads();
    }

    #pragma unroll
    for (int i = 0; i < TM; i++) {
        int r = row0 + ty * TM + i;
        if (r < M) {
            #pragma unroll
            for (int j = 0; j < TN; j += 4) {
                *reinterpret_cast<float4*>(C + (size_t)r * N + col0 + tx * TN + j) =
                    make_float4(acc[i][j], acc[i][j+1], acc[i][j+2], acc[i][j+3]);
            }
        }
    }
}

// ---------------- Kernel C: SpMM  Y = an @ X  (optionally relu) --------------
// One block per row, 256 threads = HH columns. Gathers hit L2 (X is 10 MB).
template<bool RELU>
__global__ __launch_bounds__(HH)
void k_spmm(const float* __restrict__ X, float* __restrict__ Y)
{
    const int row = blockIdx.x;
    const int c   = threadIdx.x;
    const float di = g_dinv[row];
    const int cnt = g_cnt[row];
    const int* __restrict__ cols = g_cols + (size_t)row * CAP;

    float acc = di * di * X[(size_t)row * HH + c];    // self loop
    int j = (cnt > 0) ? cols[0] : 0;
    for (int k = 0; k < cnt; k++) {
        int jn = (k + 1 < cnt) ? cols[k + 1] : 0;     // prefetch next index
        acc += di * g_dinv[j] * X[(size_t)j * HH + c];
        j = jn;
    }
    if (RELU) acc = fmaxf(acc, 0.0f);
    Y[(size_t)row * HH + c] = acc;
}

// ---------------- Kernel D: z = g @ [Wm | Ws], split outputs ----------------
// grid.x: 0 -> Wm -> out[0 : N*O), 1 -> Ws -> out[N*O : 2*N*O). N(gemm)=OO=128.
__global__ __launch_bounds__(256)
void k_out(const float* __restrict__ G, const float* __restrict__ Wm,
           const float* __restrict__ Ws, float* __restrict__ out)
{
    const int BM = 128, BN = 128, BK = 8, TM = 8, TN = 8;
    const int N = OO, K = HH, M = NN;
    __shared__ float As[BK][BM];
    __shared__ float Bs[BK][BN];

    const float* __restrict__ B = (blockIdx.x == 0) ? Wm : Ws;
    float* __restrict__ C = out + (size_t)blockIdx.x * NN * OO;

    const int tid = threadIdx.x;
    const int tx = tid % 16;
    const int ty = tid / 16;
    const int row0 = blockIdx.y * BM;

    const int aIdx = tid * 4;
    const int ar = aIdx / BK;
    const int ac = aIdx % BK;
    const int bIdx = tid * 4;
    const int br = bIdx / BN;
    const int bc = bIdx % BN;

    float acc[TM][TN];
    #pragma unroll
    for (int i = 0; i < TM; i++)
        #pragma unroll
        for (int j = 0; j < TN; j++) acc[i][j] = 0.0f;

    for (int k0 = 0; k0 < K; k0 += BK) {
        float4 av = make_float4(0.f, 0.f, 0.f, 0.f);
        if (row0 + ar < M)
            av = *reinterpret_cast<const float4*>(G + (size_t)(row0 + ar) * K + k0 + ac);
        As[ac + 0][ar] = av.x;
        As[ac + 1][ar] = av.y;
        As[ac + 2][ar] = av.z;
        As[ac + 3][ar] = av.w;

        float4 bv = *reinterpret_cast<const float4*>(B + (size_t)(k0 + br) * N + bc);
        *reinterpret_cast<float4*>(&Bs[br][bc]) = bv;
        __syncthreads();

        #pragma unroll
        for (int k = 0; k < BK; k++) {
            float a[TM], b[TN];
            #pragma unroll
            for (int i = 0; i < TM; i++) a[i] = As[k][ty * TM + i];
            #pragma unroll
            for (int j = 0; j < TN; j++) b[j] = Bs[k][tx * TN + j];
            #pragma unroll
            for (int i = 0; i < TM; i++)
                #pragma unroll
                for (int j = 0; j < TN; j++)
                    acc[i][j] += a[i] * b[j];
        }
        __syncthreads();
    }

    #pragma unroll
    for (int i = 0; i < TM; i++) {
        int r = row0 + ty * TM + i;
        if (r < M) {
            #pragma unroll
            for (int j = 0; j < TN; j += 4) {
                *reinterpret_cast<float4*>(C + (size_t)r * N + tx * TN + j) =
                    make_float4(acc[i][j], acc[i][j+1], acc[i][j+2], acc[i][j+3]);
            }
        }
    }
}

// ---------------- launch ----------------
extern "C" void kernel_launch(void* const* d_in, const int* in_sizes, int n_in,
                              void* d_out, int out_size)
{
    const float* adj = (const float*)d_in[0];   // [N, N]
    const float* x   = (const float*)d_in[1];   // [N, D]
    const float* W1  = (const float*)d_in[2];   // [D, H]
    const float* Wm  = (const float*)d_in[3];   // [H, O]
    const float* Ws  = (const float*)d_in[4];   // [H, O]
    float* out = (float*)d_out;                 // [2, N, O]: z_mean then z_log_std

    float* xw; cudaGetSymbolAddress((void**)&xw, g_xw);
    float* h;  cudaGetSymbolAddress((void**)&h,  g_h);
    float* g;  cudaGetSymbolAddress((void**)&g,  g_g);

    // 1. adjacency scan -> neighbor lists + dinv
    k_scan<<<NN, 256>>>(adj);

    // 2. xw = x @ W1   [10000,512] @ [512,256]
    k_sgemm<<<dim3(HH / 128, (NN + 127) / 128), 256>>>(x, W1, xw, NN, HH, DD);

    // 3. h = relu(an @ xw)
    k_spmm<true><<<NN, HH>>>(xw, h);

    // 4. g = an @ h
    k_spmm<false><<<NN, HH>>>(h, g);

    // 5. z_mean = g @ Wm ; z_log_std = g @ Ws
    k_out<<<dim3(2, (NN + 127) / 128), 256>>>(g, Wm, Ws, out);
}

// round 2
// speedup vs baseline: 1.2247x; 1.2247x over previous
#include <cuda_runtime.h>
#include <math.h>

#define NN 10000
#define DD 512
#define HH 256
#define OO 128
#define CAP 128          // max neighbors per row (mean ~30, sigma ~5.5 -> 17 sigma safe)
#define LCAP 16          // per-thread local buffer in scan

// ---------------- scratch (static device memory; no allocations) -------------
__device__ int   g_cols[(size_t)NN * CAP];   // neighbor column indices per row
__device__ int   g_cnt [NN];                 // nnz per row (degree = cnt+1)
__device__ float g_dinv[NN];                 // rsqrt(degree)
__device__ float g_xw  [(size_t)NN * HH];    // u  = dinv .* (x @ W1)
__device__ float g_h   [(size_t)NN * HH];    // hs = dinv .* relu(an @ xw)
__device__ float g_g   [(size_t)NN * HH];    // g  = an @ h

// ---------------- Kernel A: adjacency scan -> CSR + dinv ---------------------
// One block (256 threads) per row. Deterministic ordering via prefix scan.
__global__ void k_scan(const float* __restrict__ adj)
{
    const int row = blockIdx.x;
    const int tid = threadIdx.x;
    const float4* __restrict__ arow =
        reinterpret_cast<const float4*>(adj + (size_t)row * NN);

    int local[LCAP];
    int lc = 0;
    #pragma unroll 4
    for (int q = tid; q < NN / 4; q += 256) {
        float4 v = arow[q];
        int b = q * 4;
        if (v.x != 0.0f) { if (lc < LCAP) local[lc] = b + 0; lc++; }
        if (v.y != 0.0f) { if (lc < LCAP) local[lc] = b + 1; lc++; }
        if (v.z != 0.0f) { if (lc < LCAP) local[lc] = b + 2; lc++; }
        if (v.w != 0.0f) { if (lc < LCAP) local[lc] = b + 3; lc++; }
    }
    if (lc > LCAP) lc = LCAP;

    __shared__ int s_c[256];
    __shared__ int s_off[256];
    __shared__ int s_total;
    s_c[tid] = lc;
    __syncthreads();
    if (tid == 0) {                 // serial exclusive scan: 256 adds, negligible
        int acc = 0;
        #pragma unroll 8
        for (int i = 0; i < 256; i++) { s_off[i] = acc; acc += s_c[i]; }
        s_total = acc;
    }
    __syncthreads();

    int* __restrict__ mycols = g_cols + (size_t)row * CAP;
    int pos = s_off[tid];
    for (int i = 0; i < lc; i++) {
        int p = pos + i;
        if (p < CAP) mycols[p] = local[i];
    }
    if (tid == 0) {
        int total = s_total;
        if (total > CAP) total = CAP;
        g_cnt[row]  = total;
        g_dinv[row] = rsqrtf((float)total + 1.0f);   // degree includes self loop
    }
}

// ---------------- Kernel B: fp32 SGEMM  C[M,N] = A[M,K] @ B[K,N] -------------
// BM=BN=128, BK=8, 256 threads, 8x8 per-thread tile.
// SCALE_DINV: multiply output row r by g_dinv[r] (produces u = dinv .* (x@W1)).
template<bool SCALE_DINV>
__global__ __launch_bounds__(256)
void k_sgemm(const float* __restrict__ A, const float* __restrict__ B,
             float* __restrict__ C, int M, int N, int K)
{
    const int BM = 128, BN = 128, BK = 8, TM = 8, TN = 8;
    __shared__ float As[BK][BM];
    __shared__ float Bs[BK][BN];

    const int tid = threadIdx.x;
    const int tx = tid % 16;           // 16 x 16 thread grid
    const int ty = tid / 16;
    const int row0 = blockIdx.y * BM;
    const int col0 = blockIdx.x * BN;

    const int aIdx = tid * 4;
    const int ar = aIdx / BK;          // 0..127
    const int ac = aIdx % BK;          // 0 or 4
    const int bIdx = tid * 4;
    const int br = bIdx / BN;          // 0..7
    const int bc = bIdx % BN;

    float acc[TM][TN];
    #pragma unroll
    for (int i = 0; i < TM; i++)
        #pragma unroll
        for (int j = 0; j < TN; j++) acc[i][j] = 0.0f;

    for (int k0 = 0; k0 < K; k0 += BK) {
        float4 av = make_float4(0.f, 0.f, 0.f, 0.f);
        if (row0 + ar < M)
            av = *reinterpret_cast<const float4*>(A + (size_t)(row0 + ar) * K + k0 + ac);
        As[ac + 0][ar] = av.x;
        As[ac + 1][ar] = av.y;
        As[ac + 2][ar] = av.z;
        As[ac + 3][ar] = av.w;

        float4 bv = *reinterpret_cast<const float4*>(B + (size_t)(k0 + br) * N + col0 + bc);
        *reinterpret_cast<float4*>(&Bs[br][bc]) = bv;
        __syncthreads();

        #pragma unroll
        for (int k = 0; k < BK; k++) {
            float a[TM], b[TN];
            #pragma unroll
            for (int i = 0; i < TM; i++) a[i] = As[k][ty * TM + i];
            #pragma unroll
            for (int j = 0; j < TN; j++) b[j] = Bs[k][tx * TN + j];
            #pragma unroll
            for (int i = 0; i < TM; i++)
                #pragma unroll
                for (int j = 0; j < TN; j++)
                    acc[i][j] += a[i] * b[j];
        }
        __syncthreads();
    }

    #pragma unroll
    for (int i = 0; i < TM; i++) {
        int r = row0 + ty * TM + i;
        if (r < M) {
            float s = SCALE_DINV ? g_dinv[r] : 1.0f;
            #pragma unroll
            for (int j = 0; j < TN; j += 4) {
                *reinterpret_cast<float4*>(C + (size_t)r * N + col0 + tx * TN + j) =
                    make_float4(acc[i][j] * s, acc[i][j+1] * s,
                                acc[i][j+2] * s, acc[i][j+3] * s);
            }
        }
    }
}

// ---------------- Kernel C: SpMM  Y = f(an @ X)  with pre-scaled X -----------
// Input X is already u = dinv .* X_orig, so row-i of an@X_orig is
//   dinv_i * (u_i + sum_{j in N(i)} u_j).
// RELU_SCALE=true:  Y = dinv .* relu(an @ X_orig)   (for the mid layer: outputs hs)
// RELU_SCALE=false: Y = an @ X_orig                 (final g)
// 4 rows per block, 64 lanes per row, float4 per lane. Inner loop is pure adds.
template<bool RELU_SCALE>
__global__ __launch_bounds__(256)
void k_spmm(const float4* __restrict__ X, float4* __restrict__ Y)
{
    const int sub  = threadIdx.x >> 6;              // 0..3 row within block
    const int lane = threadIdx.x & 63;              // 0..63 column group
    const int row  = blockIdx.x * 4 + sub;

    __shared__ int s_cols[4][CAP];
    const int cnt = g_cnt[row];
    {
        const int* __restrict__ cols = g_cols + (size_t)row * CAP;
        for (int k = lane; k < cnt; k += 64) s_cols[sub][k] = cols[k];
    }
    __syncthreads();

    const int* __restrict__ sc = s_cols[sub];
    const int HV = HH / 4;                          // 64 float4 per row

    float4 a = X[(size_t)row * HV + lane];          // self term (u_row)
    float4 acc = a;

    int k = 0;
    for (; k + 4 <= cnt; k += 4) {
        int j0 = sc[k], j1 = sc[k+1], j2 = sc[k+2], j3 = sc[k+3];
        float4 v0 = X[(size_t)j0 * HV + lane];
        float4 v1 = X[(size_t)j1 * HV + lane];
        float4 v2 = X[(size_t)j2 * HV + lane];
        float4 v3 = X[(size_t)j3 * HV + lane];
        acc.x += (v0.x + v1.x) + (v2.x + v3.x);
        acc.y += (v0.y + v1.y) + (v2.y + v3.y);
        acc.z += (v0.z + v1.z) + (v2.z + v3.z);
        acc.w += (v0.w + v1.w) + (v2.w + v3.w);
    }
    for (; k < cnt; k++) {
        float4 v = X[(size_t)sc[k] * HV + lane];
        acc.x += v.x; acc.y += v.y; acc.z += v.z; acc.w += v.w;
    }

    const float di = g_dinv[row];
    float4 o;
    if (RELU_SCALE) {
        // dinv * relu(dinv * acc)
        o.x = di * fmaxf(di * acc.x, 0.0f);
        o.y = di * fmaxf(di * acc.y, 0.0f);
        o.z = di * fmaxf(di * acc.z, 0.0f);
        o.w = di * fmaxf(di * acc.w, 0.0f);
    } else {
        o.x = di * acc.x;
        o.y = di * acc.y;
        o.z = di * acc.z;
        o.w = di * acc.w;
    }
    Y[(size_t)row * HV + lane] = o;
}

// ---------------- Kernel D: z = g @ [Wm | Ws], split outputs ----------------
__global__ __launch_bounds__(256)
void k_out(const float* __restrict__ G, const float* __restrict__ Wm,
           const float* __restrict__ Ws, float* __restrict__ out)
{
    const int BM = 128, BN = 128, BK = 8, TM = 8, TN = 8;
    const int N = OO, K = HH, M = NN;
    __shared__ float As[BK][BM];
    __shared__ float Bs[BK][BN];

    const float* __restrict__ B = (blockIdx.x == 0) ? Wm : Ws;
    float* __restrict__ C = out + (size_t)blockIdx.x * NN * OO;

    const int tid = threadIdx.x;
    const int tx = tid % 16;
    const int ty = tid / 16;
    const int row0 = blockIdx.y * BM;

    const int aIdx = tid * 4;
    const int ar = aIdx / BK;
    const int ac = aIdx % BK;
    const int bIdx = tid * 4;
    const int br = bIdx / BN;
    const int bc = bIdx % BN;

    float acc[TM][TN];
    #pragma unroll
    for (int i = 0; i < TM; i++)
        #pragma unroll
        for (int j = 0; j < TN; j++) acc[i][j] = 0.0f;

    for (int k0 = 0; k0 < K; k0 += BK) {
        float4 av = make_float4(0.f, 0.f, 0.f, 0.f);
        if (row0 + ar < M)
            av = *reinterpret_cast<const float4*>(G + (size_t)(row0 + ar) * K + k0 + ac);
        As[ac + 0][ar] = av.x;
        As[ac + 1][ar] = av.y;
        As[ac + 2][ar] = av.z;
        As[ac + 3][ar] = av.w;

        float4 bv = *reinterpret_cast<const float4*>(B + (size_t)(k0 + br) * N + bc);
        *reinterpret_cast<float4*>(&Bs[br][bc]) = bv;
        __syncthreads();

        #pragma unroll
        for (int k = 0; k < BK; k++) {
            float a[TM], b[TN];
            #pragma unroll
            for (int i = 0; i < TM; i++) a[i] = As[k][ty * TM + i];
            #pragma unroll
            for (int j = 0; j < TN; j++) b[j] = Bs[k][tx * TN + j];
            #pragma unroll
            for (int i = 0; i < TM; i++)
                #pragma unroll
                for (int j = 0; j < TN; j++)
                    acc[i][j] += a[i] * b[j];
        }
        __syncthreads();
    }

    #pragma unroll
    for (int i = 0; i < TM; i++) {
        int r = row0 + ty * TM + i;
        if (r < M) {
            #pragma unroll
            for (int j = 0; j < TN; j += 4) {
                *reinterpret_cast<float4*>(C + (size_t)r * N + tx * TN + j) =
                    make_float4(acc[i][j], acc[i][j+1], acc[i][j+2], acc[i][j+3]);
            }
        }
    }
}

// ---------------- launch ----------------
extern "C" void kernel_launch(void* const* d_in, const int* in_sizes, int n_in,
                              void* d_out, int out_size)
{
    const float* adj = (const float*)d_in[0];   // [N, N]
    const float* x   = (const float*)d_in[1];   // [N, D]
    const float* W1  = (const float*)d_in[2];   // [D, H]
    const float* Wm  = (const float*)d_in[3];   // [H, O]
    const float* Ws  = (const float*)d_in[4];   // [H, O]
    float* out = (float*)d_out;                 // [2, N, O]: z_mean then z_log_std

    float* xw; cudaGetSymbolAddress((void**)&xw, g_xw);
    float* h;  cudaGetSymbolAddress((void**)&h,  g_h);
    float* g;  cudaGetSymbolAddress((void**)&g,  g_g);

    // 1. adjacency scan -> neighbor lists + dinv
    k_scan<<<NN, 256>>>(adj);

    // 2. u = dinv .* (x @ W1)   [10000,512] @ [512,256], dinv scaling in epilogue
    k_sgemm<true><<<dim3(HH / 128, (NN + 127) / 128), 256>>>(x, W1, xw, NN, HH, DD);

    // 3. hs = dinv .* relu(an @ (x@W1))
    k_spmm<true><<<NN / 4, 256>>>((const float4*)xw, (float4*)h);

    // 4. g = an @ h
    k_spmm<false><<<NN / 4, 256>>>((const float4*)h, (float4*)g);

    // 5. z_mean = g @ Wm ; z_log_std = g @ Ws
    k_out<<<dim3(2, (NN + 127) / 128), 256>>>(g, Wm, Ws, out);
}

// round 3
// speedup vs baseline: 1.8947x; 1.5471x over previous
#include <cuda_runtime.h>
#include <math.h>
#include <stdint.h>

#define NN 10000
#define DD 512
#define HH 256
#define OO 128
#define CAP 128          // max neighbors per row (mean ~30, sigma ~5.5)
#define LCAP 16          // per-thread local buffer in scan

// ---------------- scratch (static device memory; no allocations) -------------
__device__ int   g_cols[(size_t)NN * CAP];   // neighbor column indices per row
__device__ int   g_cnt [NN];                 // nnz per row (degree = cnt+1)
__device__ float g_dinv[NN];                 // rsqrt(degree)
__device__ float g_xw  [(size_t)NN * HH];    // u  = dinv .* (x @ W1)
__device__ float g_h   [(size_t)NN * HH];    // hs = dinv .* relu(an @ xw)
__device__ float g_g   [(size_t)NN * HH];    // g  = an @ h

// ---------------- Kernel A: adjacency scan -> CSR + dinv ---------------------
__global__ void k_scan(const float* __restrict__ adj)
{
    const int row = blockIdx.x;
    const int tid = threadIdx.x;
    const float4* __restrict__ arow =
        reinterpret_cast<const float4*>(adj + (size_t)row * NN);

    int local[LCAP];
    int lc = 0;
    #pragma unroll 4
    for (int q = tid; q < NN / 4; q += 256) {
        float4 v = arow[q];
        int b = q * 4;
        if (v.x != 0.0f) { if (lc < LCAP) local[lc] = b + 0; lc++; }
        if (v.y != 0.0f) { if (lc < LCAP) local[lc] = b + 1; lc++; }
        if (v.z != 0.0f) { if (lc < LCAP) local[lc] = b + 2; lc++; }
        if (v.w != 0.0f) { if (lc < LCAP) local[lc] = b + 3; lc++; }
    }
    if (lc > LCAP) lc = LCAP;

    __shared__ int s_c[256];
    __shared__ int s_off[256];
    __shared__ int s_total;
    s_c[tid] = lc;
    __syncthreads();
    if (tid == 0) {
        int acc = 0;
        #pragma unroll 8
        for (int i = 0; i < 256; i++) { s_off[i] = acc; acc += s_c[i]; }
        s_total = acc;
    }
    __syncthreads();

    int* __restrict__ mycols = g_cols + (size_t)row * CAP;
    int pos = s_off[tid];
    for (int i = 0; i < lc; i++) {
        int p = pos + i;
        if (p < CAP) mycols[p] = local[i];
    }
    if (tid == 0) {
        int total = s_total;
        if (total > CAP) total = CAP;
        g_cnt[row]  = total;
        g_dinv[row] = rsqrtf((float)total + 1.0f);
    }
}

// ---------------- tf32 helpers ----------------
__device__ __forceinline__ uint32_t f2tf32(float x)
{
    uint32_t r;
    asm("cvt.rna.tf32.f32 %0, %1;" : "=r"(r) : "f"(x));
    return r;
}

__device__ __forceinline__ void mma_tf32(float c[4],
    uint32_t a0, uint32_t a1, uint32_t a2, uint32_t a3,
    uint32_t b0, uint32_t b1)
{
    asm volatile(
        "mma.sync.aligned.m16n8k8.row.col.f32.tf32.tf32.f32 "
        "{%0,%1,%2,%3}, {%4,%5,%6,%7}, {%8,%9}, {%0,%1,%2,%3};"
        : "+f"(c[0]), "+f"(c[1]), "+f"(c[2]), "+f"(c[3])
        : "r"(a0), "r"(a1), "r"(a2), "r"(a3), "r"(b0), "r"(b1));
}

__device__ __forceinline__ int swz(int k)
{
    return ((k & 3) ^ ((k >> 2) & 3)) << 3;   // XOR swizzle offset (multiple of 8)
}

// ---------------- Kernel B: tf32 tensor-core GEMM  C = A[M,K] @ B[K,N] ------
// BM=BN=128, BK=16, 128 threads (4 warps, 64x64 warp tiles), double-buffered.
// SCALE_DINV: scale output row r by g_dinv[r].
// DUAL_B: blockIdx.x selects Bm/Bs2 and offsets C by M*NDIM (col0 = 0).
template<int KDIM, bool SCALE_DINV, bool DUAL_B>
__global__ __launch_bounds__(128)
void k_mma(const float* __restrict__ A, const float* __restrict__ Bm,
           const float* __restrict__ Bs2, float* __restrict__ C,
           int M, int NDIM)
{
    const int BM = 128, BN = 128, BK = 16;
    const int NIT = KDIM / BK;
    __shared__ uint32_t As[2][BK * BM];
    __shared__ uint32_t Bsm[2][BK * BN];

    const int tid  = threadIdx.x;
    const int lane = tid & 31;
    const int warp = tid >> 5;
    const int wm   = warp >> 1;          // 0..1
    const int wn   = warp & 1;           // 0..1
    const int gid  = lane >> 2;          // 0..7
    const int tig  = lane & 3;           // 0..3

    const int row0 = blockIdx.y * BM;
    const float* __restrict__ B = DUAL_B ? (blockIdx.x ? Bs2 : Bm) : Bm;
    const int col0 = DUAL_B ? 0 : blockIdx.x * BN;
    float* __restrict__ Cp = DUAL_B ? (C + (size_t)blockIdx.x * (size_t)M * NDIM) : C;

    // loader mappings
    const int a_m  = tid >> 2;           // 0..31 (+32j)
    const int a_kq = tid & 3;            // k-quad
    const int b_k  = tid >> 3;           // 0..15
    const int b_n4 = (tid & 7) * 4;      // (+32j)

    float acc[4][8][4];
    #pragma unroll
    for (int mt = 0; mt < 4; mt++)
        #pragma unroll
        for (int nt = 0; nt < 8; nt++)
            #pragma unroll
            for (int i = 0; i < 4; i++) acc[mt][nt][i] = 0.0f;

    float4 ra[4], rb[4];

    // ---- prologue: load tile 0 ----
    #pragma unroll
    for (int j = 0; j < 4; j++) {
        int m = a_m + 32 * j;
        int gr = row0 + m;
        ra[j] = (gr < M)
            ? *reinterpret_cast<const float4*>(A + (size_t)gr * KDIM + a_kq * 4)
            : make_float4(0.f, 0.f, 0.f, 0.f);
        rb[j] = *reinterpret_cast<const float4*>(B + (size_t)b_k * NDIM + col0 + b_n4 + 32 * j);
    }
    {
        #pragma unroll
        for (int j = 0; j < 4; j++) {
            int m = a_m + 32 * j;
            const float* v = &ra[j].x;
            #pragma unroll
            for (int i = 0; i < 4; i++) {
                int k = a_kq * 4 + i;
                As[0][k * BM + (m ^ swz(k))] = f2tf32(v[i]);
            }
            int n = b_n4 + 32 * j;
            const float* w = &rb[j].x;
            uint32_t* dst = &Bsm[0][b_k * BN + (n ^ swz(b_k))];
            #pragma unroll
            for (int i = 0; i < 4; i++) dst[i] = f2tf32(w[i]);
        }
    }
    __syncthreads();

    int st = 0;
    for (int it = 0; it < NIT; ++it) {
        // prefetch next tile into registers
        if (it + 1 < NIT) {
            int k0 = (it + 1) * BK;
            #pragma unroll
            for (int j = 0; j < 4; j++) {
                int m = a_m + 32 * j;
                int gr = row0 + m;
                ra[j] = (gr < M)
                    ? *reinterpret_cast<const float4*>(A + (size_t)gr * KDIM + k0 + a_kq * 4)
                    : make_float4(0.f, 0.f, 0.f, 0.f);
                rb[j] = *reinterpret_cast<const float4*>(B + (size_t)(k0 + b_k) * NDIM + col0 + b_n4 + 32 * j);
            }
        }

        // compute current stage
        #pragma unroll
        for (int ks = 0; ks < BK; ks += 8) {
            const int k1 = ks + tig;
            const int k2 = ks + tig + 4;
            const int sx1 = swz(k1);
            const int sx2 = swz(k2);

            uint32_t af[4][4];
            #pragma unroll
            for (int mt = 0; mt < 4; mt++) {
                int r1 = wm * 64 + mt * 16 + gid;
                af[mt][0] = As[st][k1 * BM + (r1 ^ sx1)];
                af[mt][1] = As[st][k1 * BM + ((r1 + 8) ^ sx1)];
                af[mt][2] = As[st][k2 * BM + (r1 ^ sx2)];
                af[mt][3] = As[st][k2 * BM + ((r1 + 8) ^ sx2)];
            }
            uint32_t bf[8][2];
            #pragma unroll
            for (int nt = 0; nt < 8; nt++) {
                int cn = wn * 64 + nt * 8 + gid;
                bf[nt][0] = Bsm[st][k1 * BN + (cn ^ sx1)];
                bf[nt][1] = Bsm[st][k2 * BN + (cn ^ sx2)];
            }
            #pragma unroll
            for (int mt = 0; mt < 4; mt++)
                #pragma unroll
                for (int nt = 0; nt < 8; nt++)
                    mma_tf32(acc[mt][nt], af[mt][0], af[mt][1], af[mt][2], af[mt][3],
                             bf[nt][0], bf[nt][1]);
        }

        // store prefetched tile into other stage
        if (it + 1 < NIT) {
            int so = st ^ 1;
            #pragma unroll
            for (int j = 0; j < 4; j++) {
                int m = a_m + 32 * j;
                const float* v = &ra[j].x;
                #pragma unroll
                for (int i = 0; i < 4; i++) {
                    int k = a_kq * 4 + i;
                    As[so][k * BM + (m ^ swz(k))] = f2tf32(v[i]);
                }
                int n = b_n4 + 32 * j;
                const float* w = &rb[j].x;
                uint32_t* dst = &Bsm[so][b_k * BN + (n ^ swz(b_k))];
                #pragma unroll
                for (int i = 0; i < 4; i++) dst[i] = f2tf32(w[i]);
            }
            __syncthreads();
            st = so;
        }
    }

    // ---- epilogue ----
    #pragma unroll
    for (int mt = 0; mt < 4; mt++) {
        int r1 = row0 + wm * 64 + mt * 16 + gid;
        int r2 = r1 + 8;
        float s1 = 1.0f, s2 = 1.0f;
        if (SCALE_DINV) {
            if (r1 < M) s1 = g_dinv[r1];
            if (r2 < M) s2 = g_dinv[r2];
        }
        #pragma unroll
        for (int nt = 0; nt < 8; nt++) {
            int col = col0 + wn * 64 + nt * 8 + tig * 2;
            if (r1 < M) {
                float2 v = make_float2(acc[mt][nt][0] * s1, acc[mt][nt][1] * s1);
                *reinterpret_cast<float2*>(Cp + (size_t)r1 * NDIM + col) = v;
            }
            if (r2 < M) {
                float2 v = make_float2(acc[mt][nt][2] * s2, acc[mt][nt][3] * s2);
                *reinterpret_cast<float2*>(Cp + (size_t)r2 * NDIM + col) = v;
            }
        }
    }
}

// ---------------- Kernel C: SpMM  Y = f(an @ X)  with pre-scaled X -----------
template<bool RELU_SCALE>
__global__ __launch_bounds__(256)
void k_spmm(const float4* __restrict__ X, float4* __restrict__ Y)
{
    const int sub  = threadIdx.x >> 6;              // 0..3 row within block
    const int lane = threadIdx.x & 63;              // 0..63 column group
    const int row  = blockIdx.x * 4 + sub;

    __shared__ int s_cols[4][CAP];
    const int cnt = g_cnt[row];
    {
        const int* __restrict__ cols = g_cols + (size_t)row * CAP;
        for (int k = lane; k < cnt; k += 64) s_cols[sub][k] = cols[k];
    }
    __syncthreads();

    const int* __restrict__ sc = s_cols[sub];
    const int HV = HH / 4;                          // 64 float4 per row

    float4 a = X[(size_t)row * HV + lane];          // self term
    float4 acc = a;

    int k = 0;
    for (; k + 4 <= cnt; k += 4) {
        int j0 = sc[k], j1 = sc[k+1], j2 = sc[k+2], j3 = sc[k+3];
        float4 v0 = X[(size_t)j0 * HV + lane];
        float4 v1 = X[(size_t)j1 * HV + lane];
        float4 v2 = X[(size_t)j2 * HV + lane];
        float4 v3 = X[(size_t)j3 * HV + lane];
        acc.x += (v0.x + v1.x) + (v2.x + v3.x);
        acc.y += (v0.y + v1.y) + (v2.y + v3.y);
        acc.z += (v0.z + v1.z) + (v2.z + v3.z);
        acc.w += (v0.w + v1.w) + (v2.w + v3.w);
    }
    for (; k < cnt; k++) {
        float4 v = X[(size_t)sc[k] * HV + lane];
        acc.x += v.x; acc.y += v.y; acc.z += v.z; acc.w += v.w;
    }

    const float di = g_dinv[row];
    float4 o;
    if (RELU_SCALE) {
        o.x = di * fmaxf(di * acc.x, 0.0f);
        o.y = di * fmaxf(di * acc.y, 0.0f);
        o.z = di * fmaxf(di * acc.z, 0.0f);
        o.w = di * fmaxf(di * acc.w, 0.0f);
    } else {
        o.x = di * acc.x;
        o.y = di * acc.y;
        o.z = di * acc.z;
        o.w = di * acc.w;
    }
    Y[(size_t)row * HV + lane] = o;
}

// ---------------- launch ----------------
extern "C" void kernel_launch(void* const* d_in, const int* in_sizes, int n_in,
                              void* d_out, int out_size)
{
    const float* adj = (const float*)d_in[0];   // [N, N]
    const float* x   = (const float*)d_in[1];   // [N, D]
    const float* W1  = (const float*)d_in[2];   // [D, H]
    const float* Wm  = (const float*)d_in[3];   // [H, O]
    const float* Ws  = (const float*)d_in[4];   // [H, O]
    float* out = (float*)d_out;                 // [2, N, O]

    float* xw; cudaGetSymbolAddress((void**)&xw, g_xw);
    float* h;  cudaGetSymbolAddress((void**)&h,  g_h);
    float* g;  cudaGetSymbolAddress((void**)&g,  g_g);

    const int mtiles = (NN + 127) / 128;        // 79

    // 1. adjacency scan -> neighbor lists + dinv
    k_scan<<<NN, 256>>>(adj);

    // 2. u = dinv .* (x @ W1)   [10000,512]@[512,256], tf32 tensor cores
    k_mma<DD, true, false><<<dim3(HH / 128, mtiles), 128>>>(x, W1, nullptr, xw, NN, HH);

    // 3. hs = dinv .* relu(an @ (x@W1))
    k_spmm<true><<<NN / 4, 256>>>((const float4*)xw, (float4*)h);

    // 4. g = an @ h
    k_spmm<false><<<NN / 4, 256>>>((const float4*)h, (float4*)g);

    // 5. z_mean = g @ Wm ; z_log_std = g @ Ws   (tf32 tensor cores)
    k_mma<HH, false, true><<<dim3(2, mtiles), 128>>>(g, Wm, Ws, out, NN, OO);
}

// round 4
// speedup vs baseline: 2.1981x; 1.1601x over previous
#include <cuda_runtime.h>
#include <math.h>
#include <stdint.h>

#define NN 10000
#define DD 512
#define HH 256
#define OO 128
#define CAP 128          // final merged neighbor cap per row
#define CAPH 96          // cap per half (upper / lower)
#define LCAP 16          // per-thread local buffer in scan

// ---------------- scratch (static device memory; no allocations) -------------
__device__ int   g_cols [(size_t)NN * CAP];    // merged neighbor lists
__device__ int   g_cnt  [NN];                  // merged nnz per row
__device__ float g_dinv [NN];                  // rsqrt(degree)
__device__ int   g_colsU[(size_t)NN * CAPH];   // upper-tri neighbors (own scan)
__device__ int   g_cntU [NN];
__device__ int   g_colsL[(size_t)NN * CAPH];   // lower-tri neighbors (atomic scatter)
__device__ int   g_cntL [NN];
__device__ float g_xw  [(size_t)NN * HH];      // u  = dinv .* (x @ W1)
__device__ float g_h   [(size_t)NN * HH];      // hs = dinv .* relu(an @ xw)
__device__ float g_g   [(size_t)NN * HH];      // g  = an @ h

// ---------------- Kernel Z: zero the atomic counters -------------------------
__global__ void k_zero()
{
    int i = blockIdx.x * 256 + threadIdx.x;
    if (i < NN) g_cntL[i] = 0;
}

// ---------------- Kernel A: upper-triangle scan ------------------------------
// Block b scans row b, columns (b, NN). Nonzero at (r,c):
//   - c appended to row r's U list (deterministic order via prefix scan)
//   - r appended to row c's L list (atomic; sorted later for determinism)
// Fast path: 64-byte chunks rejected with an OR tree (values are 0.0f / 1.0f).
__global__ __launch_bounds__(256)
void k_scan_ut(const float* __restrict__ adj)
{
    const int row = blockIdx.x;
    const int tid = threadIdx.x;
    const uint32_t* __restrict__ arow =
        reinterpret_cast<const uint32_t*>(adj + (size_t)row * NN);

    int local[LCAP];
    int lc = 0;

    const int start = row + 1;
    int aligned = (start + 15) & ~15;
    if (aligned > NN) aligned = NN;

    // head: scalar (< 16 elements)
    {
        int c = start + tid;
        if (c < aligned && arow[c] != 0u) { local[lc] = c; lc++; }
    }

    // body: 64B chunks (16 words); NN is a multiple of 16
    const uint4* __restrict__ arow4 = reinterpret_cast<const uint4*>(arow);
    const int base = aligned >> 4;
    const int nch  = NN >> 4;          // 625
    for (int t = base + tid; t < nch; t += 256) {
        const uint4* p = arow4 + 4 * t;
        uint4 w0 = p[0], w1 = p[1], w2 = p[2], w3 = p[3];
        uint32_t m = ((w0.x | w0.y) | (w0.z | w0.w))
                   | ((w1.x | w1.y) | (w1.z | w1.w))
                   | ((w2.x | w2.y) | (w2.z | w2.w))
                   | ((w3.x | w3.y) | (w3.z | w3.w));
        if (m != 0u) {
            const int c0 = t << 4;
            #define CHK(w, off) if ((w) != 0u) { if (lc < LCAP) local[lc] = c0 + (off); lc++; }
            CHK(w0.x, 0)  CHK(w0.y, 1)  CHK(w0.z, 2)  CHK(w0.w, 3)
            CHK(w1.x, 4)  CHK(w1.y, 5)  CHK(w1.z, 6)  CHK(w1.w, 7)
            CHK(w2.x, 8)  CHK(w2.y, 9)  CHK(w2.z, 10) CHK(w2.w, 11)
            CHK(w3.x, 12) CHK(w3.y, 13) CHK(w3.z, 14) CHK(w3.w, 15)
            #undef CHK
        }
    }
    if (lc > LCAP) lc = LCAP;

    __shared__ int s_c[256];
    __shared__ int s_off[256];
    __shared__ int s_total;
    s_c[tid] = lc;
    __syncthreads();
    if (tid == 0) {
        int acc = 0;
        #pragma unroll 8
        for (int i = 0; i < 256; i++) { s_off[i] = acc; acc += s_c[i]; }
        s_total = acc;
    }
    __syncthreads();

    // write U list (deterministic thread-major order) + scatter into L lists
    int* __restrict__ ucols = g_colsU + (size_t)row * CAPH;
    int pos = s_off[tid];
    for (int i = 0; i < lc; i++) {
        int c = local[i];
        int p = pos + i;
        if (p < CAPH) ucols[p] = c;
        int lp = atomicAdd(&g_cntL[c], 1);
        if (lp < CAPH) g_colsL[(size_t)c * CAPH + lp] = row;
    }
    if (tid == 0) {
        int total = s_total;
        if (total > CAPH) total = CAPH;
        g_cntU[row] = total;
    }
}

// ---------------- Kernel M: merge L (sorted) + U -> g_cols, cnt, dinv --------
// One warp per row. Rank-sort the atomic (L) part for determinism.
__global__ __launch_bounds__(256)
void k_merge()
{
    const int lane = threadIdx.x & 31;
    const int row  = blockIdx.x * 8 + (threadIdx.x >> 5);
    if (row >= NN) return;

    int cntL = g_cntL[row]; if (cntL > CAPH) cntL = CAPH;
    int cntU = g_cntU[row]; if (cntU > CAPH) cntU = CAPH;
    int total = cntL + cntU; if (total > CAP) total = CAP;

    const int* __restrict__ L = g_colsL + (size_t)row * CAPH;
    const int* __restrict__ U = g_colsU + (size_t)row * CAPH;
    int* __restrict__ dst = g_cols + (size_t)row * CAP;

    // sorted insert of L values (all values distinct)
    for (int s = lane; s < cntL; s += 32) {
        int v = L[s];
        int rank = 0;
        for (int j = 0; j < cntL; j++) rank += (L[j] < v) ? 1 : 0;
        if (rank < CAP) dst[rank] = v;
    }
    // append U after L
    for (int k = lane; k < cntU; k += 32) {
        int p = cntL + k;
        if (p < CAP) dst[p] = U[k];
    }
    if (lane == 0) {
        g_cnt[row]  = total;
        g_dinv[row] = rsqrtf((float)total + 1.0f);
    }
}

// ---------------- tf32 helpers ----------------
__device__ __forceinline__ uint32_t f2tf32(float x)
{
    uint32_t r;
    asm("cvt.rna.tf32.f32 %0, %1;" : "=r"(r) : "f"(x));
    return r;
}

__device__ __forceinline__ void mma_tf32(float c[4],
    uint32_t a0, uint32_t a1, uint32_t a2, uint32_t a3,
    uint32_t b0, uint32_t b1)
{
    asm volatile(
        "mma.sync.aligned.m16n8k8.row.col.f32.tf32.tf32.f32 "
        "{%0,%1,%2,%3}, {%4,%5,%6,%7}, {%8,%9}, {%0,%1,%2,%3};"
        : "+f"(c[0]), "+f"(c[1]), "+f"(c[2]), "+f"(c[3])
        : "r"(a0), "r"(a1), "r"(a2), "r"(a3), "r"(b0), "r"(b1));
}

__device__ __forceinline__ int swz(int k)
{
    return ((k & 3) ^ ((k >> 2) & 3)) << 3;
}

// ---------------- Kernel B: tf32 tensor-core GEMM  C = A[M,K] @ B[K,N] ------
template<int KDIM, bool SCALE_DINV, bool DUAL_B>
__global__ __launch_bounds__(128)
void k_mma(const float* __restrict__ A, const float* __restrict__ Bm,
           const float* __restrict__ Bs2, float* __restrict__ C,
           int M, int NDIM)
{
    const int BM = 128, BN = 128, BK = 16;
    const int NIT = KDIM / BK;
    __shared__ uint32_t As[2][BK * BM];
    __shared__ uint32_t Bsm[2][BK * BN];

    const int tid  = threadIdx.x;
    const int lane = tid & 31;
    const int warp = tid >> 5;
    const int wm   = warp >> 1;
    const int wn   = warp & 1;
    const int gid  = lane >> 2;
    const int tig  = lane & 3;

    const int row0 = blockIdx.y * BM;
    const float* __restrict__ B = DUAL_B ? (blockIdx.x ? Bs2 : Bm) : Bm;
    const int col0 = DUAL_B ? 0 : blockIdx.x * BN;
    float* __restrict__ Cp = DUAL_B ? (C + (size_t)blockIdx.x * (size_t)M * NDIM) : C;

    const int a_m  = tid >> 2;
    const int a_kq = tid & 3;
    const int b_k  = tid >> 3;
    const int b_n4 = (tid & 7) * 4;

    float acc[4][8][4];
    #pragma unroll
    for (int mt = 0; mt < 4; mt++)
        #pragma unroll
        for (int nt = 0; nt < 8; nt++)
            #pragma unroll
            for (int i = 0; i < 4; i++) acc[mt][nt][i] = 0.0f;

    float4 ra[4], rb[4];

    #pragma unroll
    for (int j = 0; j < 4; j++) {
        int m = a_m + 32 * j;
        int gr = row0 + m;
        ra[j] = (gr < M)
            ? *reinterpret_cast<const float4*>(A + (size_t)gr * KDIM + a_kq * 4)
            : make_float4(0.f, 0.f, 0.f, 0.f);
        rb[j] = *reinterpret_cast<const float4*>(B + (size_t)b_k * NDIM + col0 + b_n4 + 32 * j);
    }
    {
        #pragma unroll
        for (int j = 0; j < 4; j++) {
            int m = a_m + 32 * j;
            const float* v = &ra[j].x;
            #pragma unroll
            for (int i = 0; i < 4; i++) {
                int k = a_kq * 4 + i;
                As[0][k * BM + (m ^ swz(k))] = f2tf32(v[i]);
            }
            int n = b_n4 + 32 * j;
            const float* w = &rb[j].x;
            uint32_t* dst = &Bsm[0][b_k * BN + (n ^ swz(b_k))];
            #pragma unroll
            for (int i = 0; i < 4; i++) dst[i] = f2tf32(w[i]);
        }
    }
    __syncthreads();

    int st = 0;
    for (int it = 0; it < NIT; ++it) {
        if (it + 1 < NIT) {
            int k0 = (it + 1) * BK;
            #pragma unroll
            for (int j = 0; j < 4; j++) {
                int m = a_m + 32 * j;
                int gr = row0 + m;
                ra[j] = (gr < M)
                    ? *reinterpret_cast<const float4*>(A + (size_t)gr * KDIM + k0 + a_kq * 4)
                    : make_float4(0.f, 0.f, 0.f, 0.f);
                rb[j] = *reinterpret_cast<const float4*>(B + (size_t)(k0 + b_k) * NDIM + col0 + b_n4 + 32 * j);
            }
        }

        #pragma unroll
        for (int ks = 0; ks < BK; ks += 8) {
            const int k1 = ks + tig;
            const int k2 = ks + tig + 4;
            const int sx1 = swz(k1);
            const int sx2 = swz(k2);

            uint32_t af[4][4];
            #pragma unroll
            for (int mt = 0; mt < 4; mt++) {
                int r1 = wm * 64 + mt * 16 + gid;
                af[mt][0] = As[st][k1 * BM + (r1 ^ sx1)];
                af[mt][1] = As[st][k1 * BM + ((r1 + 8) ^ sx1)];
                af[mt][2] = As[st][k2 * BM + (r1 ^ sx2)];
                af[mt][3] = As[st][k2 * BM + ((r1 + 8) ^ sx2)];
            }
            uint32_t bf[8][2];
            #pragma unroll
            for (int nt = 0; nt < 8; nt++) {
                int cn = wn * 64 + nt * 8 + gid;
                bf[nt][0] = Bsm[st][k1 * BN + (cn ^ sx1)];
                bf[nt][1] = Bsm[st][k2 * BN + (cn ^ sx2)];
            }
            #pragma unroll
            for (int mt = 0; mt < 4; mt++)
                #pragma unroll
                for (int nt = 0; nt < 8; nt++)
                    mma_tf32(acc[mt][nt], af[mt][0], af[mt][1], af[mt][2], af[mt][3],
                             bf[nt][0], bf[nt][1]);
        }

        if (it + 1 < NIT) {
            int so = st ^ 1;
            #pragma unroll
            for (int j = 0; j < 4; j++) {
                int m = a_m + 32 * j;
                const float* v = &ra[j].x;
                #pragma unroll
                for (int i = 0; i < 4; i++) {
                    int k = a_kq * 4 + i;
                    As[so][k * BM + (m ^ swz(k))] = f2tf32(v[i]);
                }
                int n = b_n4 + 32 * j;
                const float* w = &rb[j].x;
                uint32_t* dst = &Bsm[so][b_k * BN + (n ^ swz(b_k))];
                #pragma unroll
                for (int i = 0; i < 4; i++) dst[i] = f2tf32(w[i]);
            }
            __syncthreads();
            st = so;
        }
    }

    #pragma unroll
    for (int mt = 0; mt < 4; mt++) {
        int r1 = row0 + wm * 64 + mt * 16 + gid;
        int r2 = r1 + 8;
        float s1 = 1.0f, s2 = 1.0f;
        if (SCALE_DINV) {
            if (r1 < M) s1 = g_dinv[r1];
            if (r2 < M) s2 = g_dinv[r2];
        }
        #pragma unroll
        for (int nt = 0; nt < 8; nt++) {
            int col = col0 + wn * 64 + nt * 8 + tig * 2;
            if (r1 < M) {
                float2 v = make_float2(acc[mt][nt][0] * s1, acc[mt][nt][1] * s1);
                *reinterpret_cast<float2*>(Cp + (size_t)r1 * NDIM + col) = v;
            }
            if (r2 < M) {
                float2 v = make_float2(acc[mt][nt][2] * s2, acc[mt][nt][3] * s2);
                *reinterpret_cast<float2*>(Cp + (size_t)r2 * NDIM + col) = v;
            }
        }
    }
}

// ---------------- Kernel C: SpMM  Y = f(an @ X)  with pre-scaled X -----------
template<bool RELU_SCALE>
__global__ __launch_bounds__(256)
void k_spmm(const float4* __restrict__ X, float4* __restrict__ Y)
{
    const int sub  = threadIdx.x >> 6;
    const int lane = threadIdx.x & 63;
    const int row  = blockIdx.x * 4 + sub;

    __shared__ int s_cols[4][CAP];
    const int cnt = g_cnt[row];
    {
        const int* __restrict__ cols = g_cols + (size_t)row * CAP;
        for (int k = lane; k < cnt; k += 64) s_cols[sub][k] = cols[k];
    }
    __syncthreads();

    const int* __restrict__ sc = s_cols[sub];
    const int HV = HH / 4;

    float4 a = X[(size_t)row * HV + lane];
    float4 acc = a;

    int k = 0;
    for (; k + 4 <= cnt; k += 4) {
        int j0 = sc[k], j1 = sc[k+1], j2 = sc[k+2], j3 = sc[k+3];
        float4 v0 = X[(size_t)j0 * HV + lane];
        float4 v1 = X[(size_t)j1 * HV + lane];
        float4 v2 = X[(size_t)j2 * HV + lane];
        float4 v3 = X[(size_t)j3 * HV + lane];
        acc.x += (v0.x + v1.x) + (v2.x + v3.x);
        acc.y += (v0.y + v1.y) + (v2.y + v3.y);
        acc.z += (v0.z + v1.z) + (v2.z + v3.z);
        acc.w += (v0.w + v1.w) + (v2.w + v3.w);
    }
    for (; k < cnt; k++) {
        float4 v = X[(size_t)sc[k] * HV + lane];
        acc.x += v.x; acc.y += v.y; acc.z += v.z; acc.w += v.w;
    }

    const float di = g_dinv[row];
    float4 o;
    if (RELU_SCALE) {
        o.x = di * fmaxf(di * acc.x, 0.0f);
        o.y = di * fmaxf(di * acc.y, 0.0f);
        o.z = di * fmaxf(di * acc.z, 0.0f);
        o.w = di * fmaxf(di * acc.w, 0.0f);
    } else {
        o.x = di * acc.x;
        o.y = di * acc.y;
        o.z = di * acc.z;
        o.w = di * acc.w;
    }
    Y[(size_t)row * HV + lane] = o;
}

// ---------------- launch ----------------
extern "C" void kernel_launch(void* const* d_in, const int* in_sizes, int n_in,
                              void* d_out, int out_size)
{
    const float* adj = (const float*)d_in[0];   // [N, N]
    const float* x   = (const float*)d_in[1];   // [N, D]
    const float* W1  = (const float*)d_in[2];   // [D, H]
    const float* Wm  = (const float*)d_in[3];   // [H, O]
    const float* Ws  = (const float*)d_in[4];   // [H, O]
    float* out = (float*)d_out;                 // [2, N, O]

    float* xw; cudaGetSymbolAddress((void**)&xw, g_xw);
    float* h;  cudaGetSymbolAddress((void**)&h,  g_h);
    float* g;  cudaGetSymbolAddress((void**)&g,  g_g);

    const int mtiles = (NN + 127) / 128;        // 79

    // 1. zero counters, upper-triangle scan, deterministic merge
    k_zero<<<(NN + 255) / 256, 256>>>();
    k_scan_ut<<<NN, 256>>>(adj);
    k_merge<<<(NN + 7) / 8, 256>>>();

    // 2. u = dinv .* (x @ W1)
    k_mma<DD, true, false><<<dim3(HH / 128, mtiles), 128>>>(x, W1, nullptr, xw, NN, HH);

    // 3. hs = dinv .* relu(an @ (x@W1))
    k_spmm<true><<<NN / 4, 256>>>((const float4*)xw, (float4*)h);

    // 4. g = an @ h
    k_spmm<false><<<NN / 4, 256>>>((const float4*)h, (float4*)g);

    // 5. z_mean = g @ Wm ; z_log_std = g @ Ws
    k_mma<HH, false, true><<<dim3(2, mtiles), 128>>>(g, Wm, Ws, out, NN, OO);
}